// round 1
// baseline (speedup 1.0000x reference)
#include <cuda_runtime.h>
#include <cstdint>

#define DIM 16
#define HID 32
#define TPB 256

// ---------- packed f32x2 helpers (Blackwell FFMA2/FMUL2/FADD2) ----------
union F2U { float2 f; unsigned long long u; };

__device__ __forceinline__ float2 f2fma(float2 a, float2 b, float2 c) {
    F2U A, B, C, R; A.f = a; B.f = b; C.f = c;
    asm("fma.rn.f32x2 %0, %1, %2, %3;" : "=l"(R.u) : "l"(A.u), "l"(B.u), "l"(C.u));
    return R.f;
}
__device__ __forceinline__ float2 f2mul(float2 a, float2 b) {
    F2U A, B, R; A.f = a; B.f = b;
    asm("mul.rn.f32x2 %0, %1, %2;" : "=l"(R.u) : "l"(A.u), "l"(B.u));
    return R.f;
}
__device__ __forceinline__ float2 f2add(float2 a, float2 b) {
    F2U A, B, R; A.f = a; B.f = b;
    asm("add.rn.f32x2 %0, %1, %2;" : "=l"(R.u) : "l"(A.u), "l"(B.u));
    return R.f;
}
__device__ __forceinline__ float fast_rcp(float x) {
    float r; asm("rcp.approx.f32 %0, %1;" : "=f"(r) : "f"(x)); return r;
}
__device__ __forceinline__ float fast_ex2(float x) {
    float r; asm("ex2.approx.f32 %0, %1;" : "=f"(r) : "f"(x)); return r;
}

// ---------- exact-erf GELU on a packed pair ----------
// gelu(x) = x * Phi(x),  Phi(x) = 0.5*erfc(-x/sqrt(2))
// erf via Abramowitz & Stegun 7.1.26 (|err| <= 1.5e-7), coefficients pre-halved
// so PhiHalf = t*P(t)*exp(-z^2) = 0.5*(1-erf(z)) directly, z = |x|/sqrt(2).
// Phi = (x>=0) ? 1-PhiHalf : PhiHalf, done branch-free:
//   w = -sign(x) (as +-1.0f),  b = (x>=0)?1:0 = fma(w,-0.5,0.5),  Phi = fma(w,PhiHalf,b)
__device__ __forceinline__ float2 gelu2(float2 x) {
    const float INV_SQRT2 = 0.70710678118654752f;
    const float P_AS      = 0.3275911f;
    const float A1H =  0.5f * 0.254829592f;
    const float A2H =  0.5f * -0.284496736f;
    const float A3H =  0.5f * 1.421413741f;
    const float A4H =  0.5f * -1.453152027f;
    const float A5H =  0.5f * 1.061405429f;
    const float NLOG2E = -1.4426950408889634f;

    float2 ax = make_float2(fabsf(x.x), fabsf(x.y));
    float2 z  = f2mul(ax, make_float2(INV_SQRT2, INV_SQRT2));
    float2 den = f2fma(z, make_float2(P_AS, P_AS), make_float2(1.f, 1.f));
    float2 t = make_float2(fast_rcp(den.x), fast_rcp(den.y));

    float2 q = make_float2(A5H, A5H);
    q = f2fma(q, t, make_float2(A4H, A4H));
    q = f2fma(q, t, make_float2(A3H, A3H));
    q = f2fma(q, t, make_float2(A2H, A2H));
    q = f2fma(q, t, make_float2(A1H, A1H));
    q = f2mul(q, t);

    float2 zz = f2mul(z, z);
    float2 ea = f2mul(zz, make_float2(NLOG2E, NLOG2E));
    float2 E  = make_float2(fast_ex2(ea.x), fast_ex2(ea.y));
    float2 ph = f2mul(q, E);                       // PhiHalf in [0, 0.5]

    unsigned wx = 0xBF800000u ^ (__float_as_uint(x.x) & 0x80000000u);
    unsigned wy = 0xBF800000u ^ (__float_as_uint(x.y) & 0x80000000u);
    float2 w = make_float2(__uint_as_float(wx), __uint_as_float(wy));
    float2 b = f2fma(w, make_float2(-0.5f, -0.5f), make_float2(0.5f, 0.5f));
    float2 phi = f2fma(w, ph, b);
    return f2mul(x, phi);
}

// ---------- fused kernel: one thread = one row ----------
__global__ void __launch_bounds__(TPB)
fused_ln_mlp_res(const float* __restrict__ x,
                 const float* __restrict__ ln_w, const float* __restrict__ ln_b,
                 const float* __restrict__ w1,   const float* __restrict__ b1,
                 const float* __restrict__ w2,   const float* __restrict__ b2,
                 float* __restrict__ out, int nrows)
{
    // Transposed weights in SMEM so f32x2 pairs are contiguous:
    //  sW1[d][h]  = w1[h][d] * ln_w[d]   (ln affine scale folded in)
    //  sW2[h][d]  = w2[d][h]
    //  sB1[h]     = b1[h] + sum_d w1[h][d]*ln_b[d]   (ln affine shift folded in)
    __shared__ __align__(16) float sW1[DIM][HID];
    __shared__ __align__(16) float sW2[HID][DIM];
    __shared__ __align__(16) float sB1[HID];
    __shared__ __align__(16) float sB2[DIM];

    const int t = threadIdx.x;

    #pragma unroll
    for (int i = t; i < HID * DIM; i += TPB) {
        int h = i >> 4, d = i & 15;           // i = h*16 + d
        sW1[d][h] = w1[h * DIM + d] * ln_w[d];
        sW2[h][d] = w2[d * HID + h];
    }
    if (t < HID) {
        float acc = b1[t];
        #pragma unroll
        for (int d = 0; d < DIM; d++) acc = fmaf(w1[t * DIM + d], ln_b[d], acc);
        sB1[t] = acc;
    }
    if (t >= 64 && t < 64 + DIM) sB2[t - 64] = b2[t - 64];
    __syncthreads();

    const int row = blockIdx.x * TPB + t;
    if (row >= nrows) return;

    // ---- load row (4x LDG.128, fully coalesced) ----
    const float4* xr = reinterpret_cast<const float4*>(x + (size_t)row * DIM);
    float4 v0 = xr[0], v1 = xr[1], v2 = xr[2], v3 = xr[3];
    float xv[DIM] = { v0.x, v0.y, v0.z, v0.w,  v1.x, v1.y, v1.z, v1.w,
                      v2.x, v2.y, v2.z, v2.w,  v3.x, v3.y, v3.z, v3.w };

    // ---- LayerNorm (affine folded into weights) ----
    float tr[DIM];
    #pragma unroll
    for (int d = 0; d < DIM; d++) tr[d] = xv[d];
    #pragma unroll
    for (int s = 8; s >= 1; s >>= 1)
        #pragma unroll
        for (int d = 0; d < 16; d++) if (d < s) tr[d] += tr[d + s];
    float mu = tr[0] * (1.0f / DIM);

    float ss[DIM];
    #pragma unroll
    for (int d = 0; d < DIM; d++) ss[d] = xv[d] * xv[d];
    #pragma unroll
    for (int s = 8; s >= 1; s >>= 1)
        #pragma unroll
        for (int d = 0; d < 16; d++) if (d < s) ss[d] += ss[d + s];
    float var = fmaf(-mu, mu, ss[0] * (1.0f / DIM));
    float rstd = rsqrtf(var + 1e-5f);
    float nmu = -mu * rstd;

    float xn[DIM];
    #pragma unroll
    for (int d = 0; d < DIM; d++) xn[d] = fmaf(xv[d], rstd, nmu);

    // ---- GEMM1: h1[32] = W1' @ xn + b1', packed over hidden pairs ----
    float2 acc[HID / 2];
    const float2* b1p = reinterpret_cast<const float2*>(sB1);
    #pragma unroll
    for (int hp = 0; hp < HID / 2; hp++) acc[hp] = b1p[hp];

    #pragma unroll
    for (int d = 0; d < DIM; d++) {
        float2 xd = make_float2(xn[d], xn[d]);
        const float4* wrow = reinterpret_cast<const float4*>(&sW1[d][0]); // 8x LDS.128
        #pragma unroll
        for (int q = 0; q < HID / 4; q++) {
            float4 w = wrow[q];
            acc[2 * q]     = f2fma(xd, make_float2(w.x, w.y), acc[2 * q]);
            acc[2 * q + 1] = f2fma(xd, make_float2(w.z, w.w), acc[2 * q + 1]);
        }
    }

    // ---- exact GELU (packed) ----
    float2 g[HID / 2];
    #pragma unroll
    for (int hp = 0; hp < HID / 2; hp++) g[hp] = gelu2(acc[hp]);

    // ---- GEMM2 + bias + residual, packed over output-dim pairs ----
    float2 o[DIM / 2];
    const float2* b2p = reinterpret_cast<const float2*>(sB2);
    #pragma unroll
    for (int dp = 0; dp < DIM / 2; dp++)
        o[dp] = f2add(b2p[dp], make_float2(xv[2 * dp], xv[2 * dp + 1]));

    #pragma unroll
    for (int h = 0; h < HID; h++) {
        float gh = (h & 1) ? g[h >> 1].y : g[h >> 1].x;
        float2 gd = make_float2(gh, gh);
        const float4* wrow = reinterpret_cast<const float4*>(&sW2[h][0]); // 4x LDS.128
        #pragma unroll
        for (int q = 0; q < DIM / 4; q++) {
            float4 w = wrow[q];
            o[2 * q]     = f2fma(gd, make_float2(w.x, w.y), o[2 * q]);
            o[2 * q + 1] = f2fma(gd, make_float2(w.z, w.w), o[2 * q + 1]);
        }
    }

    // ---- store (4x STG.128) ----
    float4* orow = reinterpret_cast<float4*>(out + (size_t)row * DIM);
    orow[0] = make_float4(o[0].x, o[0].y, o[1].x, o[1].y);
    orow[1] = make_float4(o[2].x, o[2].y, o[3].x, o[3].y);
    orow[2] = make_float4(o[4].x, o[4].y, o[5].x, o[5].y);
    orow[3] = make_float4(o[6].x, o[6].y, o[7].x, o[7].y);
}

extern "C" void kernel_launch(void* const* d_in, const int* in_sizes, int n_in,
                              void* d_out, int out_size)
{
    const float* x    = (const float*)d_in[0];
    const float* ln_w = (const float*)d_in[1];
    const float* ln_b = (const float*)d_in[2];
    const float* w1   = (const float*)d_in[3];
    const float* b1   = (const float*)d_in[4];
    const float* w2   = (const float*)d_in[5];
    const float* b2   = (const float*)d_in[6];
    int nrows = in_sizes[0] / DIM;
    int blocks = (nrows + TPB - 1) / TPB;
    fused_ln_mlp_res<<<blocks, TPB>>>(x, ln_w, ln_b, w1, b1, w2, b2,
                                      (float*)d_out, nrows);
}

// round 2
// speedup vs baseline: 1.7370x; 1.7370x over previous
#include <cuda_runtime.h>
#include <cstdint>

#define DIM 16
#define HID 32
#define TPB 256
#define WARPS_PER_CTA (TPB / 32)
#define TILES_PER_WARP 8
#define ROW_PAD 20            // smem row stride in floats (conflict-free for frag reads)

// ---------------- low-level helpers ----------------
__device__ __forceinline__ unsigned tf32_of(float f) {
    unsigned u; asm("cvt.rna.tf32.f32 %0, %1;" : "=r"(u) : "f"(f)); return u;
}
__device__ __forceinline__ void mma8(float& d0, float& d1, float& d2, float& d3,
                                     unsigned a0, unsigned a1, unsigned a2, unsigned a3,
                                     unsigned b0, unsigned b1) {
    asm volatile(
        "mma.sync.aligned.m16n8k8.row.col.f32.tf32.tf32.f32 "
        "{%0,%1,%2,%3}, {%4,%5,%6,%7}, {%8,%9}, {%0,%1,%2,%3};"
        : "+f"(d0), "+f"(d1), "+f"(d2), "+f"(d3)
        : "r"(a0), "r"(a1), "r"(a2), "r"(a3), "r"(b0), "r"(b1));
}
__device__ __forceinline__ float fast_rcp(float x) {
    float r; asm("rcp.approx.f32 %0, %1;" : "=f"(r) : "f"(x)); return r;
}
__device__ __forceinline__ float fast_ex2(float x) {
    float r; asm("ex2.approx.f32 %0, %1;" : "=f"(r) : "f"(x)); return r;
}

union F2U { float2 f; unsigned long long u; };
__device__ __forceinline__ float2 f2fma(float2 a, float2 b, float2 c) {
    F2U A, B, C, R; A.f = a; B.f = b; C.f = c;
    asm("fma.rn.f32x2 %0, %1, %2, %3;" : "=l"(R.u) : "l"(A.u), "l"(B.u), "l"(C.u));
    return R.f;
}
__device__ __forceinline__ float2 f2mul(float2 a, float2 b) {
    F2U A, B, R; A.f = a; B.f = b;
    asm("mul.rn.f32x2 %0, %1, %2;" : "=l"(R.u) : "l"(A.u), "l"(B.u));
    return R.f;
}

// exact-erf GELU on a packed pair (A&S 7.1.26, |err|<=1.5e-7)
__device__ __forceinline__ float2 gelu2(float2 x) {
    const float INV_SQRT2 = 0.70710678118654752f;
    const float P_AS = 0.3275911f;
    const float A1H =  0.5f * 0.254829592f;
    const float A2H =  0.5f * -0.284496736f;
    const float A3H =  0.5f * 1.421413741f;
    const float A4H =  0.5f * -1.453152027f;
    const float A5H =  0.5f * 1.061405429f;
    const float NLOG2E = -1.4426950408889634f;

    float2 ax = make_float2(fabsf(x.x), fabsf(x.y));
    float2 z  = f2mul(ax, make_float2(INV_SQRT2, INV_SQRT2));
    float2 den = f2fma(z, make_float2(P_AS, P_AS), make_float2(1.f, 1.f));
    float2 t = make_float2(fast_rcp(den.x), fast_rcp(den.y));

    float2 q = make_float2(A5H, A5H);
    q = f2fma(q, t, make_float2(A4H, A4H));
    q = f2fma(q, t, make_float2(A3H, A3H));
    q = f2fma(q, t, make_float2(A2H, A2H));
    q = f2fma(q, t, make_float2(A1H, A1H));
    q = f2mul(q, t);

    float2 zz = f2mul(z, z);
    float2 ea = f2mul(zz, make_float2(NLOG2E, NLOG2E));
    float2 E  = make_float2(fast_ex2(ea.x), fast_ex2(ea.y));
    float2 ph = f2mul(q, E);

    unsigned wx = 0xBF800000u ^ (__float_as_uint(x.x) & 0x80000000u);
    unsigned wy = 0xBF800000u ^ (__float_as_uint(x.y) & 0x80000000u);
    float2 w = make_float2(__uint_as_float(wx), __uint_as_float(wy));
    float2 b = f2fma(w, make_float2(-0.5f, -0.5f), make_float2(0.5f, 0.5f));
    float2 phi = f2fma(w, ph, b);
    return f2mul(x, phi);
}

// ---------------- fused tensor-core kernel ----------------
// One warp processes TILES_PER_WARP tiles of 16 rows.
// mma.m16n8k8 tf32 fragment maps (lane = 4g+c, g=lane/4, c=lane%4):
//   A: a0=(g,c) a1=(g+8,c) a2=(g,c+4) a3=(g+8,c+4)
//   B: b0=(k=c, n=g) b1=(k=c+4, n=g)
//   C: c0=(g,2c) c1=(g,2c+1) c2=(g+8,2c) c3=(g+8,2c+1)
__global__ void __launch_bounds__(TPB, 2)
fused_ln_mlp_mma(const float* __restrict__ x,
                 const float* __restrict__ ln_w, const float* __restrict__ ln_b,
                 const float* __restrict__ w1,   const float* __restrict__ b1,
                 const float* __restrict__ w2,   const float* __restrict__ b2,
                 float* __restrict__ out, int ntiles)
{
    __shared__ float sx[WARPS_PER_CTA][2][16 * ROW_PAD];

    const int lane = threadIdx.x & 31;
    const int wrp  = threadIdx.x >> 5;
    const int g = lane >> 2;
    const int c = lane & 3;

    // ---- per-warp weight fragments (registers, loaded once) ----
    // GEMM1: out1 = xn @ w1^T  -> B[k][n] = w1[n][k], k-tiles kt(2), n-tiles nt(4)
    unsigned B1f[2][4][2];
    #pragma unroll
    for (int kt = 0; kt < 2; kt++)
        #pragma unroll
        for (int nt = 0; nt < 4; nt++) {
            B1f[kt][nt][0] = tf32_of(w1[(nt * 8 + g) * DIM + kt * 8 + c]);
            B1f[kt][nt][1] = tf32_of(w1[(nt * 8 + g) * DIM + kt * 8 + c + 4]);
        }
    // GEMM2: out = gelu @ w2^T -> B[k][n] = w2[n][k], kt(4), nt(2)
    unsigned B2f[4][2][2];
    #pragma unroll
    for (int kt = 0; kt < 4; kt++)
        #pragma unroll
        for (int nt = 0; nt < 2; nt++) {
            B2f[kt][nt][0] = tf32_of(w2[(nt * 8 + g) * HID + kt * 8 + c]);
            B2f[kt][nt][1] = tf32_of(w2[(nt * 8 + g) * HID + kt * 8 + c + 4]);
        }
    // biases at this lane's C-columns
    float b1v[4][2], b2v[2][2];
    #pragma unroll
    for (int nt = 0; nt < 4; nt++) {
        b1v[nt][0] = b1[nt * 8 + 2 * c];
        b1v[nt][1] = b1[nt * 8 + 2 * c + 1];
    }
    #pragma unroll
    for (int nt = 0; nt < 2; nt++) {
        b2v[nt][0] = b2[nt * 8 + 2 * c];
        b2v[nt][1] = b2[nt * 8 + 2 * c + 1];
    }
    // LN affine at this lane's A-columns (c + 4j)
    float lnw[4], lnb[4];
    #pragma unroll
    for (int j = 0; j < 4; j++) { lnw[j] = ln_w[c + 4 * j]; lnb[j] = ln_b[c + 4 * j]; }

    const int gwarp = blockIdx.x * WARPS_PER_CTA + wrp;
    const long t0 = (long)gwarp * TILES_PER_WARP;

    // prefetch first tile (2x LDG.128, fully coalesced)
    float4 pv0, pv1;
    if (t0 < ntiles) {
        const float4* p = reinterpret_cast<const float4*>(x + (size_t)t0 * 16 * DIM);
        pv0 = p[lane]; pv1 = p[lane + 32];
    }

    for (int it = 0; it < TILES_PER_WARP; ++it) {
        const long tile = t0 + it;
        if (tile >= ntiles) break;
        float* S = sx[wrp][it & 1];

        // stage tile (STS.128 x2): float4 index f = lane (+32) -> row f/4, quad f%4
        {
            int r0 = lane >> 2, q0 = lane & 3;
            *reinterpret_cast<float4*>(S + r0 * ROW_PAD + q0 * 4) = pv0;
            int r1 = (lane + 32) >> 2;
            *reinterpret_cast<float4*>(S + r1 * ROW_PAD + q0 * 4) = pv1;
        }
        // prefetch next tile
        if (it + 1 < TILES_PER_WARP && tile + 1 < ntiles) {
            const float4* p = reinterpret_cast<const float4*>(x + (size_t)(tile + 1) * 16 * DIM);
            pv0 = p[lane]; pv1 = p[lane + 32];
        }
        __syncwarp();

        // ---- fragment-layout x reads (8x LDS.32, conflict-free via ROW_PAD=20) ----
        float xv0[4], xv1[4];            // rows g, g+8; cols c+4j
        #pragma unroll
        for (int j = 0; j < 4; j++) {
            xv0[j] = S[g * ROW_PAD + c + 4 * j];
            xv1[j] = S[(g + 8) * ROW_PAD + c + 4 * j];
        }

        // ---- LayerNorm stats via quad reduction ----
        float s0 = xv0[0] + xv0[1] + xv0[2] + xv0[3];
        float s1 = xv1[0] + xv1[1] + xv1[2] + xv1[3];
        float q0 = fmaf(xv0[0], xv0[0], fmaf(xv0[1], xv0[1], fmaf(xv0[2], xv0[2], xv0[3] * xv0[3])));
        float q1 = fmaf(xv1[0], xv1[0], fmaf(xv1[1], xv1[1], fmaf(xv1[2], xv1[2], xv1[3] * xv1[3])));
        s0 += __shfl_xor_sync(0xffffffffu, s0, 1); s0 += __shfl_xor_sync(0xffffffffu, s0, 2);
        s1 += __shfl_xor_sync(0xffffffffu, s1, 1); s1 += __shfl_xor_sync(0xffffffffu, s1, 2);
        q0 += __shfl_xor_sync(0xffffffffu, q0, 1); q0 += __shfl_xor_sync(0xffffffffu, q0, 2);
        q1 += __shfl_xor_sync(0xffffffffu, q1, 1); q1 += __shfl_xor_sync(0xffffffffu, q1, 2);
        const float inv = 1.0f / 16.0f;
        float mu0 = s0 * inv, mu1 = s1 * inv;
        float rstd0 = rsqrtf(fmaf(-mu0, mu0, q0 * inv) + 1e-5f);
        float rstd1 = rsqrtf(fmaf(-mu1, mu1, q1 * inv) + 1e-5f);

        // ---- A-fragments of xn (with ln affine applied) ----
        unsigned A1[2][4];
        #pragma unroll
        for (int kt = 0; kt < 2; kt++) {
            int j0 = 2 * kt, j1 = 2 * kt + 1;
            A1[kt][0] = tf32_of(fmaf((xv0[j0] - mu0) * rstd0, lnw[j0], lnb[j0]));
            A1[kt][1] = tf32_of(fmaf((xv1[j0] - mu1) * rstd1, lnw[j0], lnb[j0]));
            A1[kt][2] = tf32_of(fmaf((xv0[j1] - mu0) * rstd0, lnw[j1], lnb[j1]));
            A1[kt][3] = tf32_of(fmaf((xv1[j1] - mu1) * rstd1, lnw[j1], lnb[j1]));
        }

        // ---- GEMM1 (8 mma) + bias ----
        float C1[4][4];
        #pragma unroll
        for (int nt = 0; nt < 4; nt++) {
            C1[nt][0] = C1[nt][1] = C1[nt][2] = C1[nt][3] = 0.f;
            mma8(C1[nt][0], C1[nt][1], C1[nt][2], C1[nt][3],
                 A1[0][0], A1[0][1], A1[0][2], A1[0][3], B1f[0][nt][0], B1f[0][nt][1]);
            mma8(C1[nt][0], C1[nt][1], C1[nt][2], C1[nt][3],
                 A1[1][0], A1[1][1], A1[1][2], A1[1][3], B1f[1][nt][0], B1f[1][nt][1]);
            C1[nt][0] += b1v[nt][0]; C1[nt][1] += b1v[nt][1];
            C1[nt][2] += b1v[nt][0]; C1[nt][3] += b1v[nt][1];
        }

        // ---- GELU + C->A fragment permutation (quad shuffles) ----
        const int s0l = (lane & ~3) | (c >> 1);
        const int s1l = s0l + 2;
        const bool odd = (c & 1);
        unsigned A2[4][4];
        #pragma unroll
        for (int kt = 0; kt < 4; kt++) {        // kt = former nt of GEMM1
            float2 p0 = gelu2(make_float2(C1[kt][0], C1[kt][1]));   // row g,   cols 2c,2c+1
            float2 p1 = gelu2(make_float2(C1[kt][2], C1[kt][3]));   // row g+8
            float t00 = __shfl_sync(0xffffffffu, p0.x, s0l);
            float t01 = __shfl_sync(0xffffffffu, p0.y, s0l);
            float t10 = __shfl_sync(0xffffffffu, p1.x, s0l);
            float t11 = __shfl_sync(0xffffffffu, p1.y, s0l);
            float u00 = __shfl_sync(0xffffffffu, p0.x, s1l);
            float u01 = __shfl_sync(0xffffffffu, p0.y, s1l);
            float u10 = __shfl_sync(0xffffffffu, p1.x, s1l);
            float u11 = __shfl_sync(0xffffffffu, p1.y, s1l);
            A2[kt][0] = tf32_of(odd ? t01 : t00);
            A2[kt][1] = tf32_of(odd ? t11 : t10);
            A2[kt][2] = tf32_of(odd ? u01 : u00);
            A2[kt][3] = tf32_of(odd ? u11 : u10);
        }

        // ---- GEMM2 (8 mma) ----
        float C2[2][4];
        #pragma unroll
        for (int nt = 0; nt < 2; nt++) {
            C2[nt][0] = C2[nt][1] = C2[nt][2] = C2[nt][3] = 0.f;
            #pragma unroll
            for (int kt = 0; kt < 4; kt++)
                mma8(C2[nt][0], C2[nt][1], C2[nt][2], C2[nt][3],
                     A2[kt][0], A2[kt][1], A2[kt][2], A2[kt][3],
                     B2f[kt][nt][0], B2f[kt][nt][1]);
        }

        // ---- epilogue: + bias + residual, STG.64 x4 ----
        float* orow = out + (size_t)tile * 16 * DIM;
        #pragma unroll
        for (int nt = 0; nt < 2; nt++) {
            float2 r0 = *reinterpret_cast<const float2*>(S + g * ROW_PAD + nt * 8 + 2 * c);
            float2 r1 = *reinterpret_cast<const float2*>(S + (g + 8) * ROW_PAD + nt * 8 + 2 * c);
            float2 o0 = make_float2(C2[nt][0] + b2v[nt][0] + r0.x,
                                    C2[nt][1] + b2v[nt][1] + r0.y);
            float2 o1 = make_float2(C2[nt][2] + b2v[nt][0] + r1.x,
                                    C2[nt][3] + b2v[nt][1] + r1.y);
            *reinterpret_cast<float2*>(orow + g * DIM + nt * 8 + 2 * c) = o0;
            *reinterpret_cast<float2*>(orow + (g + 8) * DIM + nt * 8 + 2 * c) = o1;
        }
        __syncwarp();
    }
}

extern "C" void kernel_launch(void* const* d_in, const int* in_sizes, int n_in,
                              void* d_out, int out_size)
{
    const float* x    = (const float*)d_in[0];
    const float* ln_w = (const float*)d_in[1];
    const float* ln_b = (const float*)d_in[2];
    const float* w1   = (const float*)d_in[3];
    const float* b1   = (const float*)d_in[4];
    const float* w2   = (const float*)d_in[5];
    const float* b2   = (const float*)d_in[6];
    int nrows  = in_sizes[0] / DIM;
    int ntiles = nrows / 16;
    int tiles_per_cta = WARPS_PER_CTA * TILES_PER_WARP;
    int blocks = (ntiles + tiles_per_cta - 1) / tiles_per_cta;
    fused_ln_mlp_mma<<<blocks, TPB>>>(x, ln_w, ln_b, w1, b1, w2, b2,
                                      (float*)d_out, ntiles);
}

// round 3
// speedup vs baseline: 1.9480x; 1.1214x over previous
#include <cuda_runtime.h>
#include <cstdint>

#define DIM 16
#define HID 32
#define TPB 256
#define WARPS_PER_CTA (TPB / 32)
#define TILES_PER_WARP 8
#define ROW_PAD 20            // smem row stride in floats (conflict-free for frag reads)

// ---------------- low-level helpers ----------------
__device__ __forceinline__ unsigned tf32_of(float f) {
    unsigned u; asm("cvt.rna.tf32.f32 %0, %1;" : "=r"(u) : "f"(f)); return u;
}
__device__ __forceinline__ void mma8(float& d0, float& d1, float& d2, float& d3,
                                     unsigned a0, unsigned a1, unsigned a2, unsigned a3,
                                     unsigned b0, unsigned b1) {
    asm volatile(
        "mma.sync.aligned.m16n8k8.row.col.f32.tf32.tf32.f32 "
        "{%0,%1,%2,%3}, {%4,%5,%6,%7}, {%8,%9}, {%0,%1,%2,%3};"
        : "+f"(d0), "+f"(d1), "+f"(d2), "+f"(d3)
        : "r"(a0), "r"(a1), "r"(a2), "r"(a3), "r"(b0), "r"(b1));
}
__device__ __forceinline__ float fast_rcp(float x) {
    float r; asm("rcp.approx.f32 %0, %1;" : "=f"(r) : "f"(x)); return r;
}
__device__ __forceinline__ float fast_ex2(float x) {
    float r; asm("ex2.approx.f32 %0, %1;" : "=f"(r) : "f"(x)); return r;
}

union F2U { float2 f; unsigned long long u; };
__device__ __forceinline__ float2 f2fma(float2 a, float2 b, float2 c) {
    F2U A, B, C, R; A.f = a; B.f = b; C.f = c;
    asm("fma.rn.f32x2 %0, %1, %2, %3;" : "=l"(R.u) : "l"(A.u), "l"(B.u), "l"(C.u));
    return R.f;
}
__device__ __forceinline__ float2 f2mul(float2 a, float2 b) {
    F2U A, B, R; A.f = a; B.f = b;
    asm("mul.rn.f32x2 %0, %1, %2;" : "=l"(R.u) : "l"(A.u), "l"(B.u));
    return R.f;
}

// exact-erf GELU on a packed pair (A&S 7.1.25 3-term, |erf err|<=2.5e-5)
// PhiHalf = 0.5*(1-erf(z)) = 0.5*t*(a1 + a2 t + a3 t^2)*exp(-z^2), z=|x|/sqrt2,
// t = 1/(1+0.47047 z).  Phi = (x>=0) ? 1-PhiHalf : PhiHalf  (branch-free).
__device__ __forceinline__ float2 gelu2(float2 x) {
    const float INV_SQRT2 = 0.70710678118654752f;
    const float P_AS = 0.47047f;
    const float A1H =  0.5f * 0.3480242f;
    const float A2H =  0.5f * -0.0958798f;
    const float A3H =  0.5f * 0.7478556f;
    const float NLOG2E = -1.4426950408889634f;

    float2 ax = make_float2(fabsf(x.x), fabsf(x.y));
    float2 z  = f2mul(ax, make_float2(INV_SQRT2, INV_SQRT2));
    float2 den = f2fma(z, make_float2(P_AS, P_AS), make_float2(1.f, 1.f));
    float2 t = make_float2(fast_rcp(den.x), fast_rcp(den.y));

    float2 q = make_float2(A3H, A3H);
    q = f2fma(q, t, make_float2(A2H, A2H));
    q = f2fma(q, t, make_float2(A1H, A1H));
    q = f2mul(q, t);

    float2 zz = f2mul(z, z);
    float2 ea = f2mul(zz, make_float2(NLOG2E, NLOG2E));
    float2 E  = make_float2(fast_ex2(ea.x), fast_ex2(ea.y));
    float2 ph = f2mul(q, E);

    unsigned wx = 0xBF800000u ^ (__float_as_uint(x.x) & 0x80000000u);
    unsigned wy = 0xBF800000u ^ (__float_as_uint(x.y) & 0x80000000u);
    float2 w = make_float2(__uint_as_float(wx), __uint_as_float(wy));
    float2 b = f2fma(w, make_float2(-0.5f, -0.5f), make_float2(0.5f, 0.5f));
    float2 phi = f2fma(w, ph, b);
    return f2mul(x, phi);
}

// ---------------- fused tensor-core kernel ----------------
// mma.m16n8k8 tf32 fragment maps (lane = 4g+c):
//   A: a0=(g,c) a1=(g+8,c) a2=(g,c+4) a3=(g+8,c+4)
//   B: b0=(k=c,n=g) b1=(k=c+4,n=g)
//   C: c0=(g,2c) c1=(g,2c+1) c2=(g+8,2c) c3=(g+8,2c+1)
//
// GEMM2's k-axis enumerates hidden units in permuted order q(8kt+s):
//   s in 0..3 -> 8kt+2s ; s in 4..7 -> 8kt+2(s-4)+1
// so GEMM1's C fragment IS GEMM2's A fragment (a0,a1,a2,a3 = c0,c2,c1,c3),
// and only the W2 B-fragment load indexing changes (kt*8 + 2c, +1).
__global__ void __launch_bounds__(TPB, 2)
fused_ln_mlp_mma(const float* __restrict__ x,
                 const float* __restrict__ ln_w, const float* __restrict__ ln_b,
                 const float* __restrict__ w1,   const float* __restrict__ b1,
                 const float* __restrict__ w2,   const float* __restrict__ b2,
                 float* __restrict__ out, int ntiles)
{
    __shared__ float sx[WARPS_PER_CTA][2][16 * ROW_PAD];

    const int lane = threadIdx.x & 31;
    const int wrp  = threadIdx.x >> 5;
    const int g = lane >> 2;
    const int c = lane & 3;

    // ---- per-warp weight fragments (registers, loaded once) ----
    // GEMM1: B[k][n] = w1[n][k]
    unsigned B1f[2][4][2];
    #pragma unroll
    for (int kt = 0; kt < 2; kt++)
        #pragma unroll
        for (int nt = 0; nt < 4; nt++) {
            B1f[kt][nt][0] = tf32_of(w1[(nt * 8 + g) * DIM + kt * 8 + c]);
            B1f[kt][nt][1] = tf32_of(w1[(nt * 8 + g) * DIM + kt * 8 + c + 4]);
        }
    // GEMM2: B[k][n] = w2[n][q(k)] with the hidden-permutation q folded in
    unsigned B2f[4][2][2];
    #pragma unroll
    for (int kt = 0; kt < 4; kt++)
        #pragma unroll
        for (int nt = 0; nt < 2; nt++) {
            B2f[kt][nt][0] = tf32_of(w2[(nt * 8 + g) * HID + kt * 8 + 2 * c]);
            B2f[kt][nt][1] = tf32_of(w2[(nt * 8 + g) * HID + kt * 8 + 2 * c + 1]);
        }
    // biases at this lane's C-columns
    float b1v[4][2], b2v[2][2];
    #pragma unroll
    for (int nt = 0; nt < 4; nt++) {
        b1v[nt][0] = b1[nt * 8 + 2 * c];
        b1v[nt][1] = b1[nt * 8 + 2 * c + 1];
    }
    #pragma unroll
    for (int nt = 0; nt < 2; nt++) {
        b2v[nt][0] = b2[nt * 8 + 2 * c];
        b2v[nt][1] = b2[nt * 8 + 2 * c + 1];
    }
    // LN affine at this lane's A-columns (c + 4j)
    float lnw[4], lnb[4];
    #pragma unroll
    for (int j = 0; j < 4; j++) { lnw[j] = ln_w[c + 4 * j]; lnb[j] = ln_b[c + 4 * j]; }

    const int gwarp = blockIdx.x * WARPS_PER_CTA + wrp;
    const long t0 = (long)gwarp * TILES_PER_WARP;

    // prefetch first tile (2x LDG.128, fully coalesced)
    float4 pv0, pv1;
    if (t0 < ntiles) {
        const float4* p = reinterpret_cast<const float4*>(x + (size_t)t0 * 16 * DIM);
        pv0 = p[lane]; pv1 = p[lane + 32];
    }

    for (int it = 0; it < TILES_PER_WARP; ++it) {
        const long tile = t0 + it;
        if (tile >= ntiles) break;
        float* S = sx[wrp][it & 1];

        // stage tile (STS.128 x2)
        {
            int r0 = lane >> 2, q0 = lane & 3;
            *reinterpret_cast<float4*>(S + r0 * ROW_PAD + q0 * 4) = pv0;
            int r1 = (lane + 32) >> 2;
            *reinterpret_cast<float4*>(S + r1 * ROW_PAD + q0 * 4) = pv1;
        }
        // prefetch next tile
        if (it + 1 < TILES_PER_WARP && tile + 1 < ntiles) {
            const float4* p = reinterpret_cast<const float4*>(x + (size_t)(tile + 1) * 16 * DIM);
            pv0 = p[lane]; pv1 = p[lane + 32];
        }
        __syncwarp();

        // ---- fragment-layout x reads (8x LDS.32, conflict-free) ----
        float xv0[4], xv1[4];            // rows g, g+8; cols c+4j
        #pragma unroll
        for (int j = 0; j < 4; j++) {
            xv0[j] = S[g * ROW_PAD + c + 4 * j];
            xv1[j] = S[(g + 8) * ROW_PAD + c + 4 * j];
        }

        // ---- LayerNorm stats via quad reduction ----
        float s0 = xv0[0] + xv0[1] + xv0[2] + xv0[3];
        float s1 = xv1[0] + xv1[1] + xv1[2] + xv1[3];
        float q0 = fmaf(xv0[0], xv0[0], fmaf(xv0[1], xv0[1], fmaf(xv0[2], xv0[2], xv0[3] * xv0[3])));
        float q1 = fmaf(xv1[0], xv1[0], fmaf(xv1[1], xv1[1], fmaf(xv1[2], xv1[2], xv1[3] * xv1[3])));
        s0 += __shfl_xor_sync(0xffffffffu, s0, 1); s0 += __shfl_xor_sync(0xffffffffu, s0, 2);
        s1 += __shfl_xor_sync(0xffffffffu, s1, 1); s1 += __shfl_xor_sync(0xffffffffu, s1, 2);
        q0 += __shfl_xor_sync(0xffffffffu, q0, 1); q0 += __shfl_xor_sync(0xffffffffu, q0, 2);
        q1 += __shfl_xor_sync(0xffffffffu, q1, 1); q1 += __shfl_xor_sync(0xffffffffu, q1, 2);
        const float inv = 1.0f / 16.0f;
        float mu0 = s0 * inv, mu1 = s1 * inv;
        float rstd0 = rsqrtf(fmaf(-mu0, mu0, q0 * inv) + 1e-5f);
        float rstd1 = rsqrtf(fmaf(-mu1, mu1, q1 * inv) + 1e-5f);

        // ---- A-fragments of xn (ln affine applied) ----
        unsigned A1[2][4];
        #pragma unroll
        for (int kt = 0; kt < 2; kt++) {
            int j0 = 2 * kt, j1 = 2 * kt + 1;
            A1[kt][0] = tf32_of(fmaf((xv0[j0] - mu0) * rstd0, lnw[j0], lnb[j0]));
            A1[kt][1] = tf32_of(fmaf((xv1[j0] - mu1) * rstd1, lnw[j0], lnb[j0]));
            A1[kt][2] = tf32_of(fmaf((xv0[j1] - mu0) * rstd0, lnw[j1], lnb[j1]));
            A1[kt][3] = tf32_of(fmaf((xv1[j1] - mu1) * rstd1, lnw[j1], lnb[j1]));
        }

        // ---- GEMM1 (8 mma), accumulators pre-seeded with b1 ----
        float C1[4][4];
        #pragma unroll
        for (int nt = 0; nt < 4; nt++) {
            C1[nt][0] = b1v[nt][0]; C1[nt][1] = b1v[nt][1];
            C1[nt][2] = b1v[nt][0]; C1[nt][3] = b1v[nt][1];
            mma8(C1[nt][0], C1[nt][1], C1[nt][2], C1[nt][3],
                 A1[0][0], A1[0][1], A1[0][2], A1[0][3], B1f[0][nt][0], B1f[0][nt][1]);
            mma8(C1[nt][0], C1[nt][1], C1[nt][2], C1[nt][3],
                 A1[1][0], A1[1][1], A1[1][2], A1[1][3], B1f[1][nt][0], B1f[1][nt][1]);
        }

        // ---- GELU; C1 fragment IS the GEMM2 A fragment (no shuffles) ----
        unsigned A2[4][4];
        #pragma unroll
        for (int kt = 0; kt < 4; kt++) {
            float2 p0 = gelu2(make_float2(C1[kt][0], C1[kt][1]));   // row g
            float2 p1 = gelu2(make_float2(C1[kt][2], C1[kt][3]));   // row g+8
            A2[kt][0] = tf32_of(p0.x);   // (g,   k=c)   = hid 8kt+2c
            A2[kt][1] = tf32_of(p1.x);   // (g+8, k=c)
            A2[kt][2] = tf32_of(p0.y);   // (g,   k=c+4) = hid 8kt+2c+1
            A2[kt][3] = tf32_of(p1.y);   // (g+8, k=c+4)
        }

        // ---- GEMM2 (8 mma), accumulators pre-seeded with b2 + residual ----
        float C2[2][4];
        #pragma unroll
        for (int nt = 0; nt < 2; nt++) {
            float2 r0 = *reinterpret_cast<const float2*>(S + g * ROW_PAD + nt * 8 + 2 * c);
            float2 r1 = *reinterpret_cast<const float2*>(S + (g + 8) * ROW_PAD + nt * 8 + 2 * c);
            C2[nt][0] = b2v[nt][0] + r0.x; C2[nt][1] = b2v[nt][1] + r0.y;
            C2[nt][2] = b2v[nt][0] + r1.x; C2[nt][3] = b2v[nt][1] + r1.y;
            #pragma unroll
            for (int kt = 0; kt < 4; kt++)
                mma8(C2[nt][0], C2[nt][1], C2[nt][2], C2[nt][3],
                     A2[kt][0], A2[kt][1], A2[kt][2], A2[kt][3],
                     B2f[kt][nt][0], B2f[kt][nt][1]);
        }

        // ---- store (STG.64 x4) ----
        float* orow = out + (size_t)tile * 16 * DIM;
        #pragma unroll
        for (int nt = 0; nt < 2; nt++) {
            *reinterpret_cast<float2*>(orow + g * DIM + nt * 8 + 2 * c) =
                make_float2(C2[nt][0], C2[nt][1]);
            *reinterpret_cast<float2*>(orow + (g + 8) * DIM + nt * 8 + 2 * c) =
                make_float2(C2[nt][2], C2[nt][3]);
        }
        __syncwarp();
    }
}

extern "C" void kernel_launch(void* const* d_in, const int* in_sizes, int n_in,
                              void* d_out, int out_size)
{
    const float* x    = (const float*)d_in[0];
    const float* ln_w = (const float*)d_in[1];
    const float* ln_b = (const float*)d_in[2];
    const float* w1   = (const float*)d_in[3];
    const float* b1   = (const float*)d_in[4];
    const float* w2   = (const float*)d_in[5];
    const float* b2   = (const float*)d_in[6];
    int nrows  = in_sizes[0] / DIM;
    int ntiles = nrows / 16;
    int tiles_per_cta = WARPS_PER_CTA * TILES_PER_WARP;
    int blocks = (ntiles + tiles_per_cta - 1) / tiles_per_cta;
    fused_ln_mlp_mma<<<blocks, TPB>>>(x, ln_w, ln_b, w1, b1, w2, b2,
                                      (float*)d_out, ntiles);
}

// round 4
// speedup vs baseline: 2.8408x; 1.4583x over previous
#include <cuda_runtime.h>
#include <cstdint>

#define DIM 16
#define HID 32
#define TPB 256
#define WARPS_PER_CTA (TPB / 32)
#define TILES_PER_WARP 8
#define ROW_PAD 20            // smem row stride in floats (conflict-free frag reads)

// ---------------- low-level helpers ----------------
__device__ __forceinline__ unsigned tf32_rna(float f) {   // init-path only
    unsigned u; asm("cvt.rna.tf32.f32 %0, %1;" : "=r"(u) : "f"(f)); return u;
}
__device__ __forceinline__ unsigned bits(float f) { return __float_as_uint(f); }

__device__ __forceinline__ void mma8(float& d0, float& d1, float& d2, float& d3,
                                     unsigned a0, unsigned a1, unsigned a2, unsigned a3,
                                     unsigned b0, unsigned b1) {
    asm volatile(
        "mma.sync.aligned.m16n8k8.row.col.f32.tf32.tf32.f32 "
        "{%0,%1,%2,%3}, {%4,%5,%6,%7}, {%8,%9}, {%0,%1,%2,%3};"
        : "+f"(d0), "+f"(d1), "+f"(d2), "+f"(d3)
        : "r"(a0), "r"(a1), "r"(a2), "r"(a3), "r"(b0), "r"(b1));
}
__device__ __forceinline__ float fast_tanh(float x) {
    float r; asm("tanh.approx.f32 %0, %1;" : "=f"(r) : "f"(x)); return r;
}

union F2U { float2 f; unsigned long long u; };
__device__ __forceinline__ float2 f2fma(float2 a, float2 b, float2 c) {
    F2U A, B, C, R; A.f = a; B.f = b; C.f = c;
    asm("fma.rn.f32x2 %0, %1, %2, %3;" : "=l"(R.u) : "l"(A.u), "l"(B.u), "l"(C.u));
    return R.f;
}
__device__ __forceinline__ float2 f2mul(float2 a, float2 b) {
    F2U A, B, R; A.f = a; B.f = b;
    asm("mul.rn.f32x2 %0, %1, %2;" : "=l"(R.u) : "l"(A.u), "l"(B.u));
    return R.f;
}
__device__ __forceinline__ float2 f2add(float2 a, float2 b) {
    F2U A, B, R; A.f = a; B.f = b;
    asm("add.rn.f32x2 %0, %1, %2;" : "=l"(R.u) : "l"(A.u), "l"(B.u));
    return R.f;
}

// tanh-form GELU on a packed pair: 5 f32x2 ops + 2 MUFU.TANH
__device__ __forceinline__ float2 gelu2(float2 x) {
    const float C1 = 0.7978845608028654f;            // sqrt(2/pi)
    const float C2 = 0.7978845608028654f * 0.044715f;
    float2 x2 = f2mul(x, x);
    float2 inner = f2fma(x2, make_float2(C2, C2), make_float2(C1, C1));
    float2 y  = f2mul(x, inner);
    float2 t  = make_float2(fast_tanh(y.x), fast_tanh(y.y));
    float2 phi = f2fma(t, make_float2(0.5f, 0.5f), make_float2(0.5f, 0.5f));
    return f2mul(x, phi);
}

// ---------------- fused tensor-core kernel ----------------
// mma.m16n8k8 tf32 fragment maps (lane = 4g+c):
//   A: a0=(g,c) a1=(g+8,c) a2=(g,c+4) a3=(g+8,c+4)
//   B: b0=(k=c,n=g) b1=(k=c+4,n=g)
//   C: c0=(g,2c) c1=(g,2c+1) c2=(g+8,2c) c3=(g+8,2c+1)
// GEMM2's k-axis uses the hidden permutation q(8kt+s): s<4 -> 8kt+2s, s>=4 -> 8kt+2(s-4)+1,
// so GEMM1's C fragment IS GEMM2's A fragment; only the W2 B-load indexing changes.
// TF32 A-operands are raw fp32 bits (HW reads bits[31:13] => rz truncation).
__global__ void __launch_bounds__(TPB, 2)
fused_ln_mlp_mma(const float* __restrict__ x,
                 const float* __restrict__ ln_w, const float* __restrict__ ln_b,
                 const float* __restrict__ w1,   const float* __restrict__ b1,
                 const float* __restrict__ w2,   const float* __restrict__ b2,
                 float* __restrict__ out, int ntiles)
{
    __shared__ float sx[WARPS_PER_CTA][2][16 * ROW_PAD];

    const int lane = threadIdx.x & 31;
    const int wrp  = threadIdx.x >> 5;
    const int g = lane >> 2;
    const int c = lane & 3;

    // ---- per-warp weight fragments (registers, rna-converted once) ----
    unsigned B1f[2][4][2];
    #pragma unroll
    for (int kt = 0; kt < 2; kt++)
        #pragma unroll
        for (int nt = 0; nt < 4; nt++) {
            B1f[kt][nt][0] = tf32_rna(w1[(nt * 8 + g) * DIM + kt * 8 + c]);
            B1f[kt][nt][1] = tf32_rna(w1[(nt * 8 + g) * DIM + kt * 8 + c + 4]);
        }
    unsigned B2f[4][2][2];
    #pragma unroll
    for (int kt = 0; kt < 4; kt++)
        #pragma unroll
        for (int nt = 0; nt < 2; nt++) {
            B2f[kt][nt][0] = tf32_rna(w2[(nt * 8 + g) * HID + kt * 8 + 2 * c]);
            B2f[kt][nt][1] = tf32_rna(w2[(nt * 8 + g) * HID + kt * 8 + 2 * c + 1]);
        }
    float b1v[4][2];
    #pragma unroll
    for (int nt = 0; nt < 4; nt++) {
        b1v[nt][0] = b1[nt * 8 + 2 * c];
        b1v[nt][1] = b1[nt * 8 + 2 * c + 1];
    }
    float2 b2p[2];
    #pragma unroll
    for (int nt = 0; nt < 2; nt++)
        b2p[nt] = make_float2(b2[nt * 8 + 2 * c], b2[nt * 8 + 2 * c + 1]);
    // LN affine at this lane's A-columns (c + 4j), pre-duplicated into pairs
    float2 lnwp[4], lnbp[4];
    #pragma unroll
    for (int j = 0; j < 4; j++) {
        float w = ln_w[c + 4 * j], b = ln_b[c + 4 * j];
        lnwp[j] = make_float2(w, w);
        lnbp[j] = make_float2(b, b);
    }

    const int gwarp = blockIdx.x * WARPS_PER_CTA + wrp;
    const long t0 = (long)gwarp * TILES_PER_WARP;

    // prefetch first tile (2x LDG.128, fully coalesced)
    float4 pv0, pv1;
    if (t0 < ntiles) {
        const float4* p = reinterpret_cast<const float4*>(x + (size_t)t0 * 16 * DIM);
        pv0 = p[lane]; pv1 = p[lane + 32];
    }

    for (int it = 0; it < TILES_PER_WARP; ++it) {
        const long tile = t0 + it;
        if (tile >= ntiles) break;
        float* S = sx[wrp][it & 1];

        // stage tile (STS.128 x2)
        {
            int r0 = lane >> 2, q0 = lane & 3;
            *reinterpret_cast<float4*>(S + r0 * ROW_PAD + q0 * 4) = pv0;
            int r1 = (lane + 32) >> 2;
            *reinterpret_cast<float4*>(S + r1 * ROW_PAD + q0 * 4) = pv1;
        }
        // prefetch next tile
        if (it + 1 < TILES_PER_WARP && tile + 1 < ntiles) {
            const float4* p = reinterpret_cast<const float4*>(x + (size_t)(tile + 1) * 16 * DIM);
            pv0 = p[lane]; pv1 = p[lane + 32];
        }
        __syncwarp();

        // ---- fragment-layout x reads, packed (row g, row g+8) ----
        float2 xp[4];                 // xp[j] = (x[g][c+4j], x[g+8][c+4j])
        #pragma unroll
        for (int j = 0; j < 4; j++)
            xp[j] = make_float2(S[g * ROW_PAD + c + 4 * j],
                                S[(g + 8) * ROW_PAD + c + 4 * j]);

        // ---- LayerNorm stats (packed) + quad reduction ----
        float2 s = f2add(f2add(xp[0], xp[1]), f2add(xp[2], xp[3]));
        float2 q = f2mul(xp[0], xp[0]);
        q = f2fma(xp[1], xp[1], q);
        q = f2fma(xp[2], xp[2], q);
        q = f2fma(xp[3], xp[3], q);
        s.x += __shfl_xor_sync(0xffffffffu, s.x, 1); s.x += __shfl_xor_sync(0xffffffffu, s.x, 2);
        s.y += __shfl_xor_sync(0xffffffffu, s.y, 1); s.y += __shfl_xor_sync(0xffffffffu, s.y, 2);
        q.x += __shfl_xor_sync(0xffffffffu, q.x, 1); q.x += __shfl_xor_sync(0xffffffffu, q.x, 2);
        q.y += __shfl_xor_sync(0xffffffffu, q.y, 1); q.y += __shfl_xor_sync(0xffffffffu, q.y, 2);
        const float inv = 1.0f / 16.0f;
        float2 mup = f2mul(s, make_float2(inv, inv));
        float2 qi  = f2mul(q, make_float2(inv, inv));
        float rstd0 = rsqrtf(fmaf(-mup.x, mup.x, qi.x) + 1e-5f);
        float rstd1 = rsqrtf(fmaf(-mup.y, mup.y, qi.y) + 1e-5f);
        float2 rstdp = make_float2(rstd0, rstd1);
        float2 nmup  = make_float2(-mup.x * rstd0, -mup.y * rstd1);

        // xn_j = x * (rstd*lnw_j) + (nmu*lnw_j + lnb_j)   -- 3 packed ops per j
        float2 xn[4];
        #pragma unroll
        for (int j = 0; j < 4; j++) {
            float2 a = f2mul(rstdp, lnwp[j]);
            float2 b = f2fma(nmup, lnwp[j], lnbp[j]);
            xn[j] = f2fma(xp[j], a, b);
        }

        // ---- GEMM1 (8 mma), accumulators seeded with b1; raw-bit tf32 A ----
        float C1[4][4];
        #pragma unroll
        for (int nt = 0; nt < 4; nt++) {
            C1[nt][0] = b1v[nt][0]; C1[nt][1] = b1v[nt][1];
            C1[nt][2] = b1v[nt][0]; C1[nt][3] = b1v[nt][1];
            mma8(C1[nt][0], C1[nt][1], C1[nt][2], C1[nt][3],
                 bits(xn[0].x), bits(xn[0].y), bits(xn[1].x), bits(xn[1].y),
                 B1f[0][nt][0], B1f[0][nt][1]);
            mma8(C1[nt][0], C1[nt][1], C1[nt][2], C1[nt][3],
                 bits(xn[2].x), bits(xn[2].y), bits(xn[3].x), bits(xn[3].y),
                 B1f[1][nt][0], B1f[1][nt][1]);
        }

        // ---- GELU; C1 fragment IS the GEMM2 A fragment ----
        float2 ga[4], gb[4];
        #pragma unroll
        for (int kt = 0; kt < 4; kt++) {
            ga[kt] = gelu2(make_float2(C1[kt][0], C1[kt][1]));   // row g:   (a0,a2)
            gb[kt] = gelu2(make_float2(C1[kt][2], C1[kt][3]));   // row g+8: (a1,a3)
        }

        // ---- GEMM2 (8 mma), accumulators seeded with b2 + residual ----
        float C2[2][4];
        #pragma unroll
        for (int nt = 0; nt < 2; nt++) {
            float2 r0 = *reinterpret_cast<const float2*>(S + g * ROW_PAD + nt * 8 + 2 * c);
            float2 r1 = *reinterpret_cast<const float2*>(S + (g + 8) * ROW_PAD + nt * 8 + 2 * c);
            float2 s0 = f2add(b2p[nt], r0);
            float2 s1 = f2add(b2p[nt], r1);
            C2[nt][0] = s0.x; C2[nt][1] = s0.y;
            C2[nt][2] = s1.x; C2[nt][3] = s1.y;
            #pragma unroll
            for (int kt = 0; kt < 4; kt++)
                mma8(C2[nt][0], C2[nt][1], C2[nt][2], C2[nt][3],
                     bits(ga[kt].x), bits(gb[kt].x), bits(ga[kt].y), bits(gb[kt].y),
                     B2f[kt][nt][0], B2f[kt][nt][1]);
        }

        // ---- store (STG.64 x4) ----
        float* orow = out + (size_t)tile * 16 * DIM;
        #pragma unroll
        for (int nt = 0; nt < 2; nt++) {
            *reinterpret_cast<float2*>(orow + g * DIM + nt * 8 + 2 * c) =
                make_float2(C2[nt][0], C2[nt][1]);
            *reinterpret_cast<float2*>(orow + (g + 8) * DIM + nt * 8 + 2 * c) =
                make_float2(C2[nt][2], C2[nt][3]);
        }
    }
}

extern "C" void kernel_launch(void* const* d_in, const int* in_sizes, int n_in,
                              void* d_out, int out_size)
{
    const float* x    = (const float*)d_in[0];
    const float* ln_w = (const float*)d_in[1];
    const float* ln_b = (const float*)d_in[2];
    const float* w1   = (const float*)d_in[3];
    const float* b1   = (const float*)d_in[4];
    const float* w2   = (const float*)d_in[5];
    const float* b2   = (const float*)d_in[6];
    int nrows  = in_sizes[0] / DIM;
    int ntiles = nrows / 16;
    int tiles_per_cta = WARPS_PER_CTA * TILES_PER_WARP;
    int blocks = (ntiles + tiles_per_cta - 1) / tiles_per_cta;
    fused_ln_mlp_mma<<<blocks, TPB>>>(x, ln_w, ln_b, w1, b1, w2, b2,
                                      (float*)d_out, ntiles);
}